// round 3
// baseline (speedup 1.0000x reference)
#include <cuda_runtime.h>
#include <cstdint>

namespace {

constexpr int CDIM = 256;       // embed dim
constexpr int FDIM = 512;       // ffn dim
constexpr int NDIM = 1024;      // sequence (n) length per slab
constexpr int TW = 64;          // tile width (positions per tile)
constexpr int NTILES = NDIM / TW;
constexpr int NTHREADS = 256;
constexpr int PD = 16;          // weight panel depth (k)
constexpr int CS = 4 * NDIM;    // channel stride in x (floats)
constexpr float EPS = 1e-5f;

struct Smem {
  float xt[CDIM * TW];      // x tile, later x2 tile
  float yt[CDIM * TW];      // y1 / attn / y2 tile
  float hbuf[64 * TW];      // FFN hidden block
  float wp[PD * CDIM];      // weight panel
  float meanA[NDIM];
  float rstdA[NDIM];
  float qA[NDIM];           // q, then u = softmax*rstd
  float g1[CDIM];
  float be1[CDIM];
  float g2v[CDIM];
  float be2[CDIM];
  float avec[CDIM];         // w_q * g1
  float ctxv[CDIM];
  float ybar[CDIM];
  float bvv[CDIM];          // v bias
  float bov[CDIM];          // out-proj bias
  float bf2v[CDIM];         // ffn2 bias
  float bf1v[FDIM];         // ffn1 bias
  float red[32 * 65];       // LN2 cross-thread reduction (padded stride 65)
  float m2s[TW];
  float r2s[TW];
  float scratch[40];
};

__device__ __forceinline__ float warpSum(float v) {
#pragma unroll
  for (int o = 16; o; o >>= 1) v += __shfl_xor_sync(0xffffffffu, v, o);
  return v;
}

__device__ __forceinline__ float blockSum(float v, float* scr) {
  v = warpSum(v);
  const int w = threadIdx.x >> 5;
  if ((threadIdx.x & 31) == 0) scr[w] = v;
  __syncthreads();
  if (threadIdx.x == 0) {
    float t = 0.f;
#pragma unroll
    for (int i = 0; i < NTHREADS / 32; i++) t += scr[i];
    scr[8] = t;
  }
  __syncthreads();
  float r = scr[8];
  __syncthreads();
  return r;
}

__device__ __forceinline__ float blockMax(float v, float* scr) {
#pragma unroll
  for (int o = 16; o; o >>= 1) v = fmaxf(v, __shfl_xor_sync(0xffffffffu, v, o));
  const int w = threadIdx.x >> 5;
  if ((threadIdx.x & 31) == 0) scr[w] = v;
  __syncthreads();
  if (threadIdx.x == 0) {
    float t = scr[0];
#pragma unroll
    for (int i = 1; i < NTHREADS / 32; i++) t = fmaxf(t, scr[i]);
    scr[8] = t;
  }
  __syncthreads();
  float r = scr[8];
  __syncthreads();
  return r;
}

// C[256 x TW] += W[256 x kdim](row-major, ld=ldw, cols kcol0..) @ Ys[kdim x TW]
// 8x8 register tile per thread, 16-deep smem weight panels.
__device__ __forceinline__ void gemm_R256(const float* __restrict__ Wg, int ldw,
                                          int kcol0, int kdim,
                                          const float* __restrict__ Ys,
                                          float (&acc)[8][8],
                                          float* __restrict__ wp) {
  const int tid = threadIdx.x;
  const int tr = tid >> 3, tc = tid & 7;
#pragma unroll 1
  for (int kk = 0; kk < kdim; kk += PD) {
    __syncthreads();
    {
      const float* p = Wg + (size_t)tid * ldw + kcol0 + kk;
#pragma unroll
      for (int q = 0; q < PD / 4; q++) {
        float4 w4 = *(const float4*)(p + q * 4);
        wp[(q * 4 + 0) * CDIM + tid] = w4.x;
        wp[(q * 4 + 1) * CDIM + tid] = w4.y;
        wp[(q * 4 + 2) * CDIM + tid] = w4.z;
        wp[(q * 4 + 3) * CDIM + tid] = w4.w;
      }
    }
    __syncthreads();
#pragma unroll 4
    for (int k = 0; k < PD; k++) {
      const float* wr = wp + k * CDIM + tr * 8;
      float4 w0 = *(const float4*)(wr);
      float4 w1 = *(const float4*)(wr + 4);
      const float* yr = Ys + (kk + k) * TW + tc * 8;
      float4 y0 = *(const float4*)(yr);
      float4 y1 = *(const float4*)(yr + 4);
      float wv[8] = {w0.x, w0.y, w0.z, w0.w, w1.x, w1.y, w1.z, w1.w};
      float yv[8] = {y0.x, y0.y, y0.z, y0.w, y1.x, y1.y, y1.z, y1.w};
#pragma unroll
      for (int i = 0; i < 8; i++)
#pragma unroll
        for (int j = 0; j < 8; j++) acc[i][j] = fmaf(wv[i], yv[j], acc[i][j]);
    }
  }
}

// C[64 x TW] += W[64 x 256](row-major, ld=256) @ Ys[256 x TW]
// 2x8 register tile per thread.
__device__ __forceinline__ void gemm_R64(const float* __restrict__ Wg,
                                         const float* __restrict__ Ys,
                                         float (&acc)[2][8],
                                         float* __restrict__ wp) {
  const int tid = threadIdx.x;
  const int tr = tid >> 3, tc = tid & 7;
#pragma unroll 1
  for (int kk = 0; kk < CDIM; kk += PD) {
    __syncthreads();
    if (tid < 64) {
      const float* p = Wg + (size_t)tid * CDIM + kk;
#pragma unroll
      for (int q = 0; q < PD / 4; q++) {
        float4 w4 = *(const float4*)(p + q * 4);
        wp[(q * 4 + 0) * 64 + tid] = w4.x;
        wp[(q * 4 + 1) * 64 + tid] = w4.y;
        wp[(q * 4 + 2) * 64 + tid] = w4.z;
        wp[(q * 4 + 3) * 64 + tid] = w4.w;
      }
    }
    __syncthreads();
#pragma unroll 4
    for (int k = 0; k < PD; k++) {
      float2 w2 = *(const float2*)(wp + k * 64 + tr * 2);
      const float* yr = Ys + (kk + k) * TW + tc * 8;
      float4 y0 = *(const float4*)(yr);
      float4 y1 = *(const float4*)(yr + 4);
      float yv[8] = {y0.x, y0.y, y0.z, y0.w, y1.x, y1.y, y1.z, y1.w};
#pragma unroll
      for (int j = 0; j < 8; j++) {
        acc[0][j] = fmaf(w2.x, yv[j], acc[0][j]);
        acc[1][j] = fmaf(w2.y, yv[j], acc[1][j]);
      }
    }
  }
}

__global__ void __launch_bounds__(NTHREADS, 1)
fused_block_kernel(const float* __restrict__ x,
                   const float* __restrict__ ln1_w, const float* __restrict__ ln1_b,
                   const float* __restrict__ qkv_w, const float* __restrict__ qkv_b,
                   const float* __restrict__ out_w, const float* __restrict__ out_b,
                   const float* __restrict__ ln2_w, const float* __restrict__ ln2_b,
                   const float* __restrict__ ffn1_w, const float* __restrict__ ffn1_b,
                   const float* __restrict__ ffn2_w, const float* __restrict__ ffn2_b,
                   float* __restrict__ out) {
  extern __shared__ __align__(16) char smem_raw[];
  Smem* s = reinterpret_cast<Smem*>(smem_raw);
  const int tid = threadIdx.x;
  const int b = blockIdx.x >> 2;
  const int p = blockIdx.x & 3;
  const size_t base = (size_t)b * (CDIM * 4 * NDIM) + (size_t)p * NDIM;

  // ---------- Phase 0: cache small vectors ----------
  for (int i = tid; i < CDIM; i += NTHREADS) {
    float g = ln1_w[i];
    s->g1[i] = g;
    s->be1[i] = ln1_b[i];
    s->g2v[i] = ln2_w[i];
    s->be2[i] = ln2_b[i];
    s->avec[i] = qkv_w[i] * g;              // row 0 of qkv_w = w_q
    s->bvv[i] = qkv_b[1 + CDIM + i];
    s->bov[i] = out_b[i];
    s->bf2v[i] = ffn2_b[i];
  }
  for (int i = tid; i < FDIM; i += NTHREADS) s->bf1v[i] = ffn1_b[i];
  float aP = 0.f, bP = 0.f;
  for (int i = tid; i < CDIM; i += NTHREADS) {
    aP += qkv_w[i] * ln1_w[i];
    bP += qkv_w[i] * ln1_b[i];
  }
  __syncthreads();
  const float A_ = blockSum(aP, s->scratch);
  const float B0_ = blockSum(bP, s->scratch) + qkv_b[0];

  // ---------- Phase 1: LN stats + q per column ----------
#pragma unroll 1
  for (int pass = 0; pass < NDIM / NTHREADS; pass++) {
    const int n = pass * NTHREADS + tid;
    const float* xp = x + base + n;
    float s1 = 0.f, s2 = 0.f, sq = 0.f;
#pragma unroll 8
    for (int c = 0; c < CDIM; c++) {
      float v = __ldg(xp + (size_t)c * CS);
      s1 += v;
      s2 = fmaf(v, v, s2);
      sq = fmaf(s->avec[c], v, sq);
    }
    const float mean = s1 * (1.0f / 256.0f);
    const float var = s2 * (1.0f / 256.0f) - mean * mean;
    const float rstd = rsqrtf(var + EPS);
    s->meanA[n] = mean;
    s->rstdA[n] = rstd;
    s->qA[n] = rstd * (sq - mean * A_) + B0_;
  }
  __syncthreads();

  // ---------- Phase 2: softmax over n, ybar, ctx ----------
  {
    float mx = -3.4e38f;
#pragma unroll
    for (int k = 0; k < 4; k++) mx = fmaxf(mx, s->qA[k * NTHREADS + tid]);
    mx = blockMax(mx, s->scratch);
    float ev[4];
    float ssum = 0.f, usum = 0.f;
#pragma unroll
    for (int k = 0; k < 4; k++) {
      const int i = k * NTHREADS + tid;
      float e = expf(s->qA[i] - mx);
      ev[k] = e;
      ssum += e;
      usum = fmaf(e, s->rstdA[i] * s->meanA[i], usum);
    }
    ssum = blockSum(ssum, s->scratch);
    usum = blockSum(usum, s->scratch);
    const float inv = 1.0f / ssum;
    const float U = usum * inv;
#pragma unroll
    for (int k = 0; k < 4; k++) {
      const int i = k * NTHREADS + tid;
      s->qA[i] = ev[k] * inv * s->rstdA[i];   // u_n = softmax_n * rstd_n
    }
    __syncthreads();

    const int w = tid >> 5, l = tid & 31;
    // ybar_c = g1_c * (X_row_c . u - U) + be1_c
    for (int r = w; r < CDIM; r += 8) {
      const float* xr = x + base + (size_t)r * CS;
      float acc = 0.f;
#pragma unroll 4
      for (int i = l; i < NDIM; i += 32) acc = fmaf(__ldg(xr + i), s->qA[i], acc);
      acc = warpSum(acc);
      if (l == 0) s->ybar[r] = s->g1[r] * (acc - U) + s->be1[r];
    }
    __syncthreads();
    // ctx = W_k @ ybar + b_k   (rows 1..256 of qkv)
    for (int r = w; r < CDIM; r += 8) {
      const float* wr = qkv_w + (size_t)(1 + r) * CDIM;
      float acc = 0.f;
#pragma unroll 4
      for (int i = l; i < CDIM; i += 32) acc = fmaf(__ldg(wr + i), s->ybar[i], acc);
      acc = warpSum(acc);
      if (l == 0) s->ctxv[r] = acc + qkv_b[1 + r];
    }
    __syncthreads();
  }

  // ---------- Phase 3: tiled main pipeline ----------
  const int tr = tid >> 3, tc = tid & 7;
#pragma unroll 1
  for (int it = 0; it < NTILES; it++) {
    const int n0 = it * TW;

    // load x tile + build y1 tile
    for (int idx = tid; idx < CDIM * (TW / 4); idx += NTHREADS) {
      const int r = idx >> 4;
      const int j = (idx & 15) << 2;
      float4 xv = *(const float4*)(x + base + (size_t)r * CS + n0 + j);
      *(float4*)&s->xt[r * TW + j] = xv;
      float4 mv = *(const float4*)&s->meanA[n0 + j];
      float4 rv = *(const float4*)&s->rstdA[n0 + j];
      const float g = s->g1[r], be = s->be1[r];
      float4 yv;
      yv.x = (xv.x - mv.x) * rv.x * g + be;
      yv.y = (xv.y - mv.y) * rv.y * g + be;
      yv.z = (xv.z - mv.z) * rv.z * g + be;
      yv.w = (xv.w - mv.w) * rv.w * g + be;
      *(float4*)&s->yt[r * TW + j] = yv;
    }

    float acc[8][8];
#pragma unroll
    for (int i = 0; i < 8; i++)
#pragma unroll
      for (int j = 0; j < 8; j++) acc[i][j] = 0.f;

    // G1: V = W_v @ Y1   (rows 257..512 of qkv)
    gemm_R256(qkv_w + (size_t)(1 + CDIM) * CDIM, CDIM, 0, CDIM, s->yt, acc, s->wp);
    __syncthreads();  // all reads of yt done before overwrite
#pragma unroll
    for (int i = 0; i < 8; i++) {
      const int r = tr * 8 + i;
      const float bv = s->bvv[r], cx = s->ctxv[r];
      float4 o0, o1;
      o0.x = fmaxf(acc[i][0] + bv, 0.f) * cx;
      o0.y = fmaxf(acc[i][1] + bv, 0.f) * cx;
      o0.z = fmaxf(acc[i][2] + bv, 0.f) * cx;
      o0.w = fmaxf(acc[i][3] + bv, 0.f) * cx;
      o1.x = fmaxf(acc[i][4] + bv, 0.f) * cx;
      o1.y = fmaxf(acc[i][5] + bv, 0.f) * cx;
      o1.z = fmaxf(acc[i][6] + bv, 0.f) * cx;
      o1.w = fmaxf(acc[i][7] + bv, 0.f) * cx;
      *(float4*)&s->yt[r * TW + tc * 8] = o0;
      *(float4*)&s->yt[r * TW + tc * 8 + 4] = o1;
    }

#pragma unroll
    for (int i = 0; i < 8; i++)
#pragma unroll
      for (int j = 0; j < 8; j++) acc[i][j] = 0.f;

    // G2: O = W_out @ attn ; x2 = x + O + b ; LN2 partials in registers
    gemm_R256(out_w, CDIM, 0, CDIM, s->yt, acc, s->wp);
    __syncthreads();
    float s1l[8], s2l[8];
#pragma unroll
    for (int j = 0; j < 8; j++) { s1l[j] = 0.f; s2l[j] = 0.f; }
#pragma unroll
    for (int i = 0; i < 8; i++) {
      const int r = tr * 8 + i;
      const float bo = s->bov[r];
      float4 xa = *(const float4*)&s->xt[r * TW + tc * 8];
      float4 xb = *(const float4*)&s->xt[r * TW + tc * 8 + 4];
      float xs[8] = {xa.x, xa.y, xa.z, xa.w, xb.x, xb.y, xb.z, xb.w};
#pragma unroll
      for (int j = 0; j < 8; j++) {
        const float v = acc[i][j] + bo + xs[j];
        acc[i][j] = v;                      // acc now holds x2
        s1l[j] += v;
        s2l[j] = fmaf(v, v, s2l[j]);
      }
      float4 w0 = {acc[i][0], acc[i][1], acc[i][2], acc[i][3]};
      float4 w1 = {acc[i][4], acc[i][5], acc[i][6], acc[i][7]};
      *(float4*)&s->xt[r * TW + tc * 8] = w0;     // xt now holds x2
      *(float4*)&s->xt[r * TW + tc * 8 + 4] = w1;
    }
    // LN2 stats: reduce 32 row-group partials per column
#pragma unroll
    for (int j = 0; j < 8; j++) s->red[tr * 65 + tc * 8 + j] = s1l[j];
    __syncthreads();
    {
      const int w = tid >> 5, l = tid & 31;
#pragma unroll
      for (int cc = 0; cc < 8; cc++) {
        const int col = w * 8 + cc;
        float v = warpSum(s->red[l * 65 + col]);
        if (l == 0) s->m2s[col] = v * (1.0f / 256.0f);
      }
    }
    __syncthreads();
#pragma unroll
    for (int j = 0; j < 8; j++) s->red[tr * 65 + tc * 8 + j] = s2l[j];
    __syncthreads();
    {
      const int w = tid >> 5, l = tid & 31;
#pragma unroll
      for (int cc = 0; cc < 8; cc++) {
        const int col = w * 8 + cc;
        float v = warpSum(s->red[l * 65 + col]);
        if (l == 0) {
          const float m = s->m2s[col];
          s->r2s[col] = rsqrtf(v * (1.0f / 256.0f) - m * m + EPS);
        }
      }
    }
    __syncthreads();
    // y2 into yt (from x2 held in registers)
#pragma unroll
    for (int i = 0; i < 8; i++) {
      const int r = tr * 8 + i;
      const float g = s->g2v[r], be = s->be2[r];
      float4 y0, y1;
      y0.x = (acc[i][0] - s->m2s[tc * 8 + 0]) * s->r2s[tc * 8 + 0] * g + be;
      y0.y = (acc[i][1] - s->m2s[tc * 8 + 1]) * s->r2s[tc * 8 + 1] * g + be;
      y0.z = (acc[i][2] - s->m2s[tc * 8 + 2]) * s->r2s[tc * 8 + 2] * g + be;
      y0.w = (acc[i][3] - s->m2s[tc * 8 + 3]) * s->r2s[tc * 8 + 3] * g + be;
      y1.x = (acc[i][4] - s->m2s[tc * 8 + 4]) * s->r2s[tc * 8 + 4] * g + be;
      y1.y = (acc[i][5] - s->m2s[tc * 8 + 5]) * s->r2s[tc * 8 + 5] * g + be;
      y1.z = (acc[i][6] - s->m2s[tc * 8 + 6]) * s->r2s[tc * 8 + 6] * g + be;
      y1.w = (acc[i][7] - s->m2s[tc * 8 + 7]) * s->r2s[tc * 8 + 7] * g + be;
      *(float4*)&s->yt[r * TW + tc * 8] = y0;
      *(float4*)&s->yt[r * TW + tc * 8 + 4] = y1;
    }

    // FFN: H in 64-row blocks, G4 accumulates across blocks
    float accR[8][8];
#pragma unroll
    for (int i = 0; i < 8; i++)
#pragma unroll
      for (int j = 0; j < 8; j++) accR[i][j] = 0.f;

#pragma unroll 1
    for (int hb = 0; hb < FDIM / 64; hb++) {
      float a3[2][8];
#pragma unroll
      for (int i = 0; i < 2; i++)
#pragma unroll
        for (int j = 0; j < 8; j++) a3[i][j] = 0.f;
      gemm_R64(ffn1_w + (size_t)hb * 64 * CDIM, s->yt, a3, s->wp);
      __syncthreads();
#pragma unroll
      for (int i = 0; i < 2; i++) {
        const int hr = tr * 2 + i;
        const float bf = s->bf1v[hb * 64 + hr];
        float hv[8];
#pragma unroll
        for (int j = 0; j < 8; j++) {
          float h = a3[i][j] + bf;
          hv[j] = (h > 0.f) ? h : 0.1f * h;   // leaky_relu 0.1
        }
        float4 h0 = {hv[0], hv[1], hv[2], hv[3]};
        float4 h1 = {hv[4], hv[5], hv[6], hv[7]};
        *(float4*)&s->hbuf[hr * TW + tc * 8] = h0;
        *(float4*)&s->hbuf[hr * TW + tc * 8 + 4] = h1;
      }
      // G4 partial: accR += W2[:, hb*64 .. +64] @ Hblk
      gemm_R256(ffn2_w, FDIM, hb * 64, 64, s->hbuf, accR, s->wp);
    }

    // final epilogue: out = x2 + W2@H + b2
    __syncthreads();
#pragma unroll
    for (int i = 0; i < 8; i++) {
      const int r = tr * 8 + i;
      const float bf = s->bf2v[r];
      float4 xa = *(const float4*)&s->xt[r * TW + tc * 8];
      float4 xb = *(const float4*)&s->xt[r * TW + tc * 8 + 4];
      float4 o0, o1;
      o0.x = accR[i][0] + bf + xa.x;
      o0.y = accR[i][1] + bf + xa.y;
      o0.z = accR[i][2] + bf + xa.z;
      o0.w = accR[i][3] + bf + xa.w;
      o1.x = accR[i][4] + bf + xb.x;
      o1.y = accR[i][5] + bf + xb.y;
      o1.z = accR[i][6] + bf + xb.z;
      o1.w = accR[i][7] + bf + xb.w;
      float* op = out + base + (size_t)r * CS + n0 + tc * 8;
      *(float4*)op = o0;
      *(float4*)(op + 4) = o1;
    }
    __syncthreads();  // protect xt/yt/red reuse next tile
  }
}

}  // namespace

extern "C" void kernel_launch(void* const* d_in, const int* in_sizes, int n_in,
                              void* d_out, int out_size) {
  const float* x      = (const float*)d_in[0];
  const float* ln1_w  = (const float*)d_in[1];
  const float* ln1_b  = (const float*)d_in[2];
  const float* qkv_w  = (const float*)d_in[3];
  const float* qkv_b  = (const float*)d_in[4];
  const float* out_w  = (const float*)d_in[5];
  const float* out_b  = (const float*)d_in[6];
  const float* ln2_w  = (const float*)d_in[7];
  const float* ln2_b  = (const float*)d_in[8];
  const float* ffn1_w = (const float*)d_in[9];
  const float* ffn1_b = (const float*)d_in[10];
  const float* ffn2_w = (const float*)d_in[11];
  const float* ffn2_b = (const float*)d_in[12];
  float* out = (float*)d_out;

  const int B = in_sizes[0] / (CDIM * 4 * NDIM);
  const int grid = B * 4;
  const int smem = (int)sizeof(Smem);
  cudaFuncSetAttribute(fused_block_kernel,
                       cudaFuncAttributeMaxDynamicSharedMemorySize, smem);
  fused_block_kernel<<<grid, NTHREADS, smem>>>(
      x, ln1_w, ln1_b, qkv_w, qkv_b, out_w, out_b, ln2_w, ln2_b,
      ffn1_w, ffn1_b, ffn2_w, ffn2_b, out);
}

// round 4
// speedup vs baseline: 1.7121x; 1.7121x over previous
#include <cuda_runtime.h>
#include <cstdint>

namespace {

constexpr int CDIM = 256;
constexpr int FDIM = 512;
constexpr int NDIM = 1024;
constexpr int TW = 128;            // tile width (positions per tile)
constexpr int NTILES = NDIM / TW;  // 8
constexpr int NTHREADS = 256;
constexpr int PD = 16;             // weight panel depth (k)
constexpr int CS = 4 * NDIM;       // channel stride in x (floats)
constexpr float EPS = 1e-5f;

struct Smem {
  float yt[CDIM * TW];        // y1 / attn / y2 tile (128 KB)
  float hbuf[64 * TW];        // FFN hidden block; aliased as LN2 reduction buf
  float wp[2 * PD * CDIM];    // double-buffered weight panel (32 KB)
  float meanA[NDIM];
  float rstdA[NDIM];
  float qA[NDIM];             // q, then u = softmax*rstd
  float g1[CDIM], be1[CDIM], g2v[CDIM], be2[CDIM], avec[CDIM];
  float ctxv[CDIM], ybar[CDIM], bvv[CDIM], bov[CDIM], bf2v[CDIM];
  float bf1v[FDIM];
  float m2s[TW], r2s[TW];
  float scratch[40];
};

__device__ __forceinline__ float warpSum(float v) {
#pragma unroll
  for (int o = 16; o; o >>= 1) v += __shfl_xor_sync(0xffffffffu, v, o);
  return v;
}

__device__ __forceinline__ float blockSum(float v, float* scr) {
  v = warpSum(v);
  const int w = threadIdx.x >> 5;
  if ((threadIdx.x & 31) == 0) scr[w] = v;
  __syncthreads();
  if (threadIdx.x == 0) {
    float t = 0.f;
#pragma unroll
    for (int i = 0; i < NTHREADS / 32; i++) t += scr[i];
    scr[8] = t;
  }
  __syncthreads();
  float r = scr[8];
  __syncthreads();
  return r;
}

__device__ __forceinline__ float blockMax(float v, float* scr) {
#pragma unroll
  for (int o = 16; o; o >>= 1) v = fmaxf(v, __shfl_xor_sync(0xffffffffu, v, o));
  const int w = threadIdx.x >> 5;
  if ((threadIdx.x & 31) == 0) scr[w] = v;
  __syncthreads();
  if (threadIdx.x == 0) {
    float t = scr[0];
#pragma unroll
    for (int i = 1; i < NTHREADS / 32; i++) t = fmaxf(t, scr[i]);
    scr[8] = t;
  }
  __syncthreads();
  float r = scr[8];
  __syncthreads();
  return r;
}

__device__ __forceinline__ void storePanel256(float* w0, int tid,
                                              const float4& s0, const float4& s1,
                                              const float4& s2, const float4& s3) {
  w0[0 * CDIM + tid] = s0.x;  w0[1 * CDIM + tid] = s0.y;
  w0[2 * CDIM + tid] = s0.z;  w0[3 * CDIM + tid] = s0.w;
  w0[4 * CDIM + tid] = s1.x;  w0[5 * CDIM + tid] = s1.y;
  w0[6 * CDIM + tid] = s1.z;  w0[7 * CDIM + tid] = s1.w;
  w0[8 * CDIM + tid] = s2.x;  w0[9 * CDIM + tid] = s2.y;
  w0[10 * CDIM + tid] = s2.z; w0[11 * CDIM + tid] = s2.w;
  w0[12 * CDIM + tid] = s3.x; w0[13 * CDIM + tid] = s3.y;
  w0[14 * CDIM + tid] = s3.z; w0[15 * CDIM + tid] = s3.w;
}

// acc[256 x TW] += W[256 x kdim](row-major, ld=ldw, cols kcol0..) @ Ys[kdim x TW]
// 16x8 register tile/thread; double-buffered pipelined weight panels; 1 bar/panel.
__device__ __forceinline__ void gemm_T16x8(const float* __restrict__ Wg, int ldw,
                                           int kcol0, int kdim,
                                           const float* __restrict__ Ys,
                                           float (&acc)[16][8],
                                           float* __restrict__ wp) {
  const int tid = threadIdx.x;
  const int tr = tid >> 4, tc = tid & 15;
  const float* gp = Wg + (size_t)tid * ldw + kcol0;
  float4 st0 = *(const float4*)(gp + 0);
  float4 st1 = *(const float4*)(gp + 4);
  float4 st2 = *(const float4*)(gp + 8);
  float4 st3 = *(const float4*)(gp + 12);
  storePanel256(wp, tid, st0, st1, st2, st3);
  __syncthreads();
  const int P = kdim / PD;
#pragma unroll 1
  for (int p = 0; p < P; p++) {
    if (p + 1 < P) {
      const float* g2 = gp + (p + 1) * PD;
      st0 = *(const float4*)(g2 + 0);
      st1 = *(const float4*)(g2 + 4);
      st2 = *(const float4*)(g2 + 8);
      st3 = *(const float4*)(g2 + 12);
    }
    const float* wb = wp + (p & 1) * (PD * CDIM);
    const float* yb = Ys + p * PD * TW;
#pragma unroll 4
    for (int k = 0; k < PD; k++) {
      const float* wr = wb + k * CDIM + tr * 16;
      float4 a0 = *(const float4*)(wr);
      float4 a1 = *(const float4*)(wr + 4);
      float4 a2 = *(const float4*)(wr + 8);
      float4 a3v = *(const float4*)(wr + 12);
      const float* yr = yb + k * TW + tc * 8;
      float4 b0 = *(const float4*)(yr);
      float4 b1 = *(const float4*)(yr + 4);
      float wv[16] = {a0.x, a0.y, a0.z, a0.w, a1.x, a1.y, a1.z, a1.w,
                      a2.x, a2.y, a2.z, a2.w, a3v.x, a3v.y, a3v.z, a3v.w};
      float yv[8] = {b0.x, b0.y, b0.z, b0.w, b1.x, b1.y, b1.z, b1.w};
#pragma unroll
      for (int i = 0; i < 16; i++)
#pragma unroll
        for (int j = 0; j < 8; j++) acc[i][j] = fmaf(wv[i], yv[j], acc[i][j]);
    }
    if (p + 1 < P)
      storePanel256(wp + ((p + 1) & 1) * (PD * CDIM), tid, st0, st1, st2, st3);
    __syncthreads();
  }
}

// acc[64 x TW] += W[64 x 256](row-major, ld=256) @ Ys[256 x TW]; 4x8 tile/thread.
__device__ __forceinline__ void gemm_T4x8(const float* __restrict__ Wg,
                                          const float* __restrict__ Ys,
                                          float (&acc)[4][8],
                                          float* __restrict__ wp) {
  const int tid = threadIdx.x;
  const int rg = tid >> 4, tc = tid & 15;
  const int lrow = tid >> 2, lk = (tid & 3) * 4;
  const float* gp = Wg + (size_t)lrow * CDIM + lk;
  float4 st = *(const float4*)(gp);
  {
    float* w0 = wp;
    w0[(lk + 0) * 64 + lrow] = st.x;
    w0[(lk + 1) * 64 + lrow] = st.y;
    w0[(lk + 2) * 64 + lrow] = st.z;
    w0[(lk + 3) * 64 + lrow] = st.w;
  }
  __syncthreads();
  const int P = CDIM / PD;
#pragma unroll 1
  for (int p = 0; p < P; p++) {
    if (p + 1 < P) st = *(const float4*)(gp + (p + 1) * PD);
    const float* wb = wp + (p & 1) * (PD * 64);
    const float* yb = Ys + p * PD * TW;
#pragma unroll 4
    for (int k = 0; k < PD; k++) {
      float4 a0 = *(const float4*)(wb + k * 64 + rg * 4);
      const float* yr = yb + k * TW + tc * 8;
      float4 b0 = *(const float4*)(yr);
      float4 b1 = *(const float4*)(yr + 4);
      float wv[4] = {a0.x, a0.y, a0.z, a0.w};
      float yv[8] = {b0.x, b0.y, b0.z, b0.w, b1.x, b1.y, b1.z, b1.w};
#pragma unroll
      for (int i = 0; i < 4; i++)
#pragma unroll
        for (int j = 0; j < 8; j++) acc[i][j] = fmaf(wv[i], yv[j], acc[i][j]);
    }
    if (p + 1 < P) {
      float* wn = wp + ((p + 1) & 1) * (PD * 64);
      wn[(lk + 0) * 64 + lrow] = st.x;
      wn[(lk + 1) * 64 + lrow] = st.y;
      wn[(lk + 2) * 64 + lrow] = st.z;
      wn[(lk + 3) * 64 + lrow] = st.w;
    }
    __syncthreads();
  }
}

__global__ void __launch_bounds__(NTHREADS, 1)
fused_block_kernel(const float* __restrict__ x,
                   const float* __restrict__ ln1_w, const float* __restrict__ ln1_b,
                   const float* __restrict__ qkv_w, const float* __restrict__ qkv_b,
                   const float* __restrict__ out_w, const float* __restrict__ out_b,
                   const float* __restrict__ ln2_w, const float* __restrict__ ln2_b,
                   const float* __restrict__ ffn1_w, const float* __restrict__ ffn1_b,
                   const float* __restrict__ ffn2_w, const float* __restrict__ ffn2_b,
                   float* __restrict__ out) {
  extern __shared__ __align__(16) char smem_raw[];
  Smem* s = reinterpret_cast<Smem*>(smem_raw);
  const int tid = threadIdx.x;
  const int b = blockIdx.x >> 2;
  const int p = blockIdx.x & 3;
  const size_t base = (size_t)b * (CDIM * 4 * NDIM) + (size_t)p * NDIM;

  // ---------- Phase 0: cache small vectors ----------
  for (int i = tid; i < CDIM; i += NTHREADS) {
    float g = ln1_w[i];
    s->g1[i] = g;
    s->be1[i] = ln1_b[i];
    s->g2v[i] = ln2_w[i];
    s->be2[i] = ln2_b[i];
    s->avec[i] = qkv_w[i] * g;   // row 0 of qkv_w = w_q
    s->bvv[i] = qkv_b[1 + CDIM + i];
    s->bov[i] = out_b[i];
    s->bf2v[i] = ffn2_b[i];
  }
  for (int i = tid; i < FDIM; i += NTHREADS) s->bf1v[i] = ffn1_b[i];
  float aP = 0.f, bP = 0.f;
  for (int i = tid; i < CDIM; i += NTHREADS) {
    aP += qkv_w[i] * ln1_w[i];
    bP += qkv_w[i] * ln1_b[i];
  }
  __syncthreads();
  const float A_ = blockSum(aP, s->scratch);
  const float B0_ = blockSum(bP, s->scratch) + qkv_b[0];

  // ---------- Phase 1: LN stats + q per column ----------
#pragma unroll 1
  for (int pass = 0; pass < NDIM / NTHREADS; pass++) {
    const int n = pass * NTHREADS + tid;
    const float* xp = x + base + n;
    float s1 = 0.f, s2 = 0.f, sq = 0.f;
#pragma unroll 8
    for (int c = 0; c < CDIM; c++) {
      float v = __ldg(xp + (size_t)c * CS);
      s1 += v;
      s2 = fmaf(v, v, s2);
      sq = fmaf(s->avec[c], v, sq);
    }
    const float mean = s1 * (1.0f / 256.0f);
    const float var = s2 * (1.0f / 256.0f) - mean * mean;
    const float rstd = rsqrtf(var + EPS);
    s->meanA[n] = mean;
    s->rstdA[n] = rstd;
    s->qA[n] = rstd * (sq - mean * A_) + B0_;
  }
  __syncthreads();

  // ---------- Phase 2: softmax over n, ybar, ctx ----------
  {
    float mx = -3.4e38f;
#pragma unroll
    for (int k = 0; k < 4; k++) mx = fmaxf(mx, s->qA[k * NTHREADS + tid]);
    mx = blockMax(mx, s->scratch);
    float ev[4];
    float ssum = 0.f, usum = 0.f;
#pragma unroll
    for (int k = 0; k < 4; k++) {
      const int i = k * NTHREADS + tid;
      float e = expf(s->qA[i] - mx);
      ev[k] = e;
      ssum += e;
      usum = fmaf(e, s->rstdA[i] * s->meanA[i], usum);
    }
    ssum = blockSum(ssum, s->scratch);
    usum = blockSum(usum, s->scratch);
    const float inv = 1.0f / ssum;
    const float U = usum * inv;
#pragma unroll
    for (int k = 0; k < 4; k++) {
      const int i = k * NTHREADS + tid;
      s->qA[i] = ev[k] * inv * s->rstdA[i];   // u_n = softmax_n * rstd_n
    }
    __syncthreads();

    const int w = tid >> 5, l = tid & 31;
    for (int r = w; r < CDIM; r += 8) {
      const float* xr = x + base + (size_t)r * CS;
      float acc = 0.f;
#pragma unroll 4
      for (int i = l; i < NDIM; i += 32) acc = fmaf(__ldg(xr + i), s->qA[i], acc);
      acc = warpSum(acc);
      if (l == 0) s->ybar[r] = s->g1[r] * (acc - U) + s->be1[r];
    }
    __syncthreads();
    for (int r = w; r < CDIM; r += 8) {
      const float* wr = qkv_w + (size_t)(1 + r) * CDIM;
      float acc = 0.f;
#pragma unroll 4
      for (int i = l; i < CDIM; i += 32) acc = fmaf(__ldg(wr + i), s->ybar[i], acc);
      acc = warpSum(acc);
      if (l == 0) s->ctxv[r] = acc + qkv_b[1 + r];
    }
    __syncthreads();
  }

  // ---------- Phase 3: tiled main pipeline ----------
  const int tr = tid >> 4, tc = tid & 15;
#pragma unroll 1
  for (int it = 0; it < NTILES; it++) {
    const int n0 = it * TW;

    // build y1 tile (yt)
    for (int idx = tid; idx < CDIM * (TW / 4); idx += NTHREADS) {
      const int r = idx >> 5;
      const int j = (idx & 31) << 2;
      float4 xv = *(const float4*)(x + base + (size_t)r * CS + n0 + j);
      float4 mv = *(const float4*)&s->meanA[n0 + j];
      float4 rv = *(const float4*)&s->rstdA[n0 + j];
      const float g = s->g1[r], be = s->be1[r];
      float4 yv;
      yv.x = (xv.x - mv.x) * rv.x * g + be;
      yv.y = (xv.y - mv.y) * rv.y * g + be;
      yv.z = (xv.z - mv.z) * rv.z * g + be;
      yv.w = (xv.w - mv.w) * rv.w * g + be;
      *(float4*)&s->yt[r * TW + j] = yv;
    }
    // (gemm prologue barrier orders yt writes vs reads)

    float acc[16][8];
#pragma unroll
    for (int i = 0; i < 16; i++)
#pragma unroll
      for (int j = 0; j < 8; j++) acc[i][j] = 0.f;

    // G1: V = W_v @ Y1 (rows 257..512 of qkv)
    gemm_T16x8(qkv_w + (size_t)(1 + CDIM) * CDIM, CDIM, 0, CDIM, s->yt, acc, s->wp);
#pragma unroll
    for (int i = 0; i < 16; i++) {
      const int r = tr * 16 + i;
      const float bv = s->bvv[r], cx = s->ctxv[r];
      float4 o0, o1;
      o0.x = fmaxf(acc[i][0] + bv, 0.f) * cx;
      o0.y = fmaxf(acc[i][1] + bv, 0.f) * cx;
      o0.z = fmaxf(acc[i][2] + bv, 0.f) * cx;
      o0.w = fmaxf(acc[i][3] + bv, 0.f) * cx;
      o1.x = fmaxf(acc[i][4] + bv, 0.f) * cx;
      o1.y = fmaxf(acc[i][5] + bv, 0.f) * cx;
      o1.z = fmaxf(acc[i][6] + bv, 0.f) * cx;
      o1.w = fmaxf(acc[i][7] + bv, 0.f) * cx;
      *(float4*)&s->yt[r * TW + tc * 8] = o0;
      *(float4*)&s->yt[r * TW + tc * 8 + 4] = o1;
    }

#pragma unroll
    for (int i = 0; i < 16; i++)
#pragma unroll
      for (int j = 0; j < 8; j++) acc[i][j] = 0.f;

    // G2: O = W_out @ attn ; x2 = x + O + b ; LN2 stats
    gemm_T16x8(out_w, CDIM, 0, CDIM, s->yt, acc, s->wp);
    float s1l[8], s2l[8];
#pragma unroll
    for (int j = 0; j < 8; j++) { s1l[j] = 0.f; s2l[j] = 0.f; }
#pragma unroll
    for (int i = 0; i < 16; i++) {
      const int r = tr * 16 + i;
      const float bo = s->bov[r];
      const float* xp = x + base + (size_t)r * CS + n0 + tc * 8;
      float4 xa = *(const float4*)(xp);
      float4 xb = *(const float4*)(xp + 4);
      float xs[8] = {xa.x, xa.y, xa.z, xa.w, xb.x, xb.y, xb.z, xb.w};
#pragma unroll
      for (int j = 0; j < 8; j++) {
        const float v = acc[i][j] + bo + xs[j];
        acc[i][j] = v;   // acc now holds x2 (kept in regs through FFN)
        s1l[j] += v;
        s2l[j] = fmaf(v, v, s2l[j]);
      }
    }
    // LN2 reduction (aliased into hbuf)
    {
      float* red1 = s->hbuf;
      float* red2 = s->hbuf + 16 * 132;
#pragma unroll
      for (int j = 0; j < 8; j++) {
        red1[tr * 132 + tc * 8 + j] = s1l[j];
        red2[tr * 132 + tc * 8 + j] = s2l[j];
      }
      __syncthreads();
      if (tid < TW) {
        float m = 0.f, vv = 0.f;
#pragma unroll
        for (int g = 0; g < 16; g++) {
          m += red1[g * 132 + tid];
          vv += red2[g * 132 + tid];
        }
        m *= (1.0f / 256.0f);
        vv = vv * (1.0f / 256.0f) - m * m;
        s->m2s[tid] = m;
        s->r2s[tid] = rsqrtf(vv + EPS);
      }
      __syncthreads();
    }
    // y2 into yt
#pragma unroll
    for (int i = 0; i < 16; i++) {
      const int r = tr * 16 + i;
      const float g = s->g2v[r], be = s->be2[r];
      float4 y0, y1;
      y0.x = (acc[i][0] - s->m2s[tc * 8 + 0]) * s->r2s[tc * 8 + 0] * g + be;
      y0.y = (acc[i][1] - s->m2s[tc * 8 + 1]) * s->r2s[tc * 8 + 1] * g + be;
      y0.z = (acc[i][2] - s->m2s[tc * 8 + 2]) * s->r2s[tc * 8 + 2] * g + be;
      y0.w = (acc[i][3] - s->m2s[tc * 8 + 3]) * s->r2s[tc * 8 + 3] * g + be;
      y1.x = (acc[i][4] - s->m2s[tc * 8 + 4]) * s->r2s[tc * 8 + 4] * g + be;
      y1.y = (acc[i][5] - s->m2s[tc * 8 + 5]) * s->r2s[tc * 8 + 5] * g + be;
      y1.z = (acc[i][6] - s->m2s[tc * 8 + 6]) * s->r2s[tc * 8 + 6] * g + be;
      y1.w = (acc[i][7] - s->m2s[tc * 8 + 7]) * s->r2s[tc * 8 + 7] * g + be;
      *(float4*)&s->yt[r * TW + tc * 8] = y0;
      *(float4*)&s->yt[r * TW + tc * 8 + 4] = y1;
    }

    // FFN: acc (holding x2) accumulates ffn2 output; H in 64-row blocks
#pragma unroll 1
    for (int hb = 0; hb < FDIM / 64; hb++) {
      float a3[4][8];
#pragma unroll
      for (int i = 0; i < 4; i++)
#pragma unroll
        for (int j = 0; j < 8; j++) a3[i][j] = 0.f;
      gemm_T4x8(ffn1_w + (size_t)hb * 64 * CDIM, s->yt, a3, s->wp);
#pragma unroll
      for (int i = 0; i < 4; i++) {
        const int hr = (tid >> 4) * 4 + i;
        const float bf = s->bf1v[hb * 64 + hr];
        float hv[8];
#pragma unroll
        for (int j = 0; j < 8; j++) {
          float h = a3[i][j] + bf;
          hv[j] = (h > 0.f) ? h : 0.1f * h;
        }
        float4 h0 = {hv[0], hv[1], hv[2], hv[3]};
        float4 h1 = {hv[4], hv[5], hv[6], hv[7]};
        *(float4*)&s->hbuf[hr * TW + tc * 8] = h0;
        *(float4*)&s->hbuf[hr * TW + tc * 8 + 4] = h1;
      }
      // G4 partial: acc += W2[:, hb*64..+64) @ Hblk  (prologue bar orders hbuf)
      gemm_T16x8(ffn2_w, FDIM, hb * 64, 64, s->hbuf, acc, s->wp);
    }

    // final: out = x2 + ffn2(H) + b2   (all in acc)
#pragma unroll
    for (int i = 0; i < 16; i++) {
      const int r = tr * 16 + i;
      const float bf = s->bf2v[r];
      float4 o0, o1;
      o0.x = acc[i][0] + bf;
      o0.y = acc[i][1] + bf;
      o0.z = acc[i][2] + bf;
      o0.w = acc[i][3] + bf;
      o1.x = acc[i][4] + bf;
      o1.y = acc[i][5] + bf;
      o1.z = acc[i][6] + bf;
      o1.w = acc[i][7] + bf;
      float* op = out + base + (size_t)r * CS + n0 + tc * 8;
      *(float4*)op = o0;
      *(float4*)(op + 4) = o1;
    }
    // next tile's yt writes are ordered by the next gemm prologue barrier;
    // after the last G4 loop-end barrier no thread reads yt/hbuf/wp again.
  }
}

}  // namespace

extern "C" void kernel_launch(void* const* d_in, const int* in_sizes, int n_in,
                              void* d_out, int out_size) {
  const float* x      = (const float*)d_in[0];
  const float* ln1_w  = (const float*)d_in[1];
  const float* ln1_b  = (const float*)d_in[2];
  const float* qkv_w  = (const float*)d_in[3];
  const float* qkv_b  = (const float*)d_in[4];
  const float* out_w  = (const float*)d_in[5];
  const float* out_b  = (const float*)d_in[6];
  const float* ln2_w  = (const float*)d_in[7];
  const float* ln2_b  = (const float*)d_in[8];
  const float* ffn1_w = (const float*)d_in[9];
  const float* ffn1_b = (const float*)d_in[10];
  const float* ffn2_w = (const float*)d_in[11];
  const float* ffn2_b = (const float*)d_in[12];
  float* out = (float*)d_out;

  const int B = in_sizes[0] / (CDIM * 4 * NDIM);
  const int grid = B * 4;
  const int smem = (int)sizeof(Smem);
  cudaFuncSetAttribute(fused_block_kernel,
                       cudaFuncAttributeMaxDynamicSharedMemorySize, smem);
  fused_block_kernel<<<grid, NTHREADS, smem>>>(
      x, ln1_w, ln1_b, qkv_w, qkv_b, out_w, out_b, ln2_w, ln2_b,
      ffn1_w, ffn1_b, ffn2_w, ffn2_b, out);
}

// round 6
// speedup vs baseline: 1.7264x; 1.0083x over previous
#include <cuda_runtime.h>
#include <cstdint>

namespace {

using u64 = unsigned long long;

constexpr int CDIM = 256;
constexpr int FDIM = 512;
constexpr int NDIM = 1024;
constexpr int TW = 128;            // tile width (positions per tile)
constexpr int NTILES = NDIM / TW;  // 8
constexpr int NTHREADS = 256;
constexpr int PD = 16;             // weight panel depth (k)
constexpr int CS = 4 * NDIM;       // channel stride in x (floats)
constexpr float EPS = 1e-5f;

struct Smem {
  float yt[CDIM * TW];        // y1 / attn / y2 tile (128 KB)
  float hbuf[64 * TW];        // FFN hidden block; aliased as LN2 reduction buf
  float wp[2 * PD * CDIM];    // double-buffered weight panel (32 KB)
  float meanA[NDIM];
  float rstdA[NDIM];
  float qA[NDIM];             // q, then u = softmax*rstd
  float g1[CDIM], be1[CDIM], g2v[CDIM], be2[CDIM], avec[CDIM];
  float ctxv[CDIM], ybar[CDIM], bvv[CDIM], bov[CDIM], bf2v[CDIM];
  float bf1v[FDIM];
  float m2s[TW], r2s[TW];
  float scratch[40];
};

// ---- packed fp32x2 helpers (FFMA2 path, sm_100a) ----
__device__ __forceinline__ u64 fma2(u64 a, u64 b, u64 c) {
  u64 d;
  asm("fma.rn.f32x2 %0, %1, %2, %3;" : "=l"(d) : "l"(a), "l"(b), "l"(c));
  return d;
}
__device__ __forceinline__ u64 pack2(float lo, float hi) {
  u64 d;
  asm("mov.b64 %0, {%1, %2};" : "=l"(d) : "f"(lo), "f"(hi));
  return d;
}
__device__ __forceinline__ float2 unpack2(u64 v) {
  float lo, hi;
  asm("mov.b64 {%0, %1}, %2;" : "=f"(lo), "=f"(hi) : "l"(v));
  return make_float2(lo, hi);
}

__device__ __forceinline__ float warpSum(float v) {
#pragma unroll
  for (int o = 16; o; o >>= 1) v += __shfl_xor_sync(0xffffffffu, v, o);
  return v;
}

__device__ __forceinline__ float blockSum(float v, float* scr) {
  v = warpSum(v);
  const int w = threadIdx.x >> 5;
  if ((threadIdx.x & 31) == 0) scr[w] = v;
  __syncthreads();
  if (threadIdx.x == 0) {
    float t = 0.f;
#pragma unroll
    for (int i = 0; i < NTHREADS / 32; i++) t += scr[i];
    scr[8] = t;
  }
  __syncthreads();
  float r = scr[8];
  __syncthreads();
  return r;
}

__device__ __forceinline__ float blockMax(float v, float* scr) {
#pragma unroll
  for (int o = 16; o; o >>= 1) v = fmaxf(v, __shfl_xor_sync(0xffffffffu, v, o));
  const int w = threadIdx.x >> 5;
  if ((threadIdx.x & 31) == 0) scr[w] = v;
  __syncthreads();
  if (threadIdx.x == 0) {
    float t = scr[0];
#pragma unroll
    for (int i = 1; i < NTHREADS / 32; i++) t = fmaxf(t, scr[i]);
    scr[8] = t;
  }
  __syncthreads();
  float r = scr[8];
  __syncthreads();
  return r;
}

__device__ __forceinline__ void storePanel256(float* w0, int tid,
                                              const float4& s0, const float4& s1,
                                              const float4& s2, const float4& s3) {
  w0[0 * CDIM + tid] = s0.x;  w0[1 * CDIM + tid] = s0.y;
  w0[2 * CDIM + tid] = s0.z;  w0[3 * CDIM + tid] = s0.w;
  w0[4 * CDIM + tid] = s1.x;  w0[5 * CDIM + tid] = s1.y;
  w0[6 * CDIM + tid] = s1.z;  w0[7 * CDIM + tid] = s1.w;
  w0[8 * CDIM + tid] = s2.x;  w0[9 * CDIM + tid] = s2.y;
  w0[10 * CDIM + tid] = s2.z; w0[11 * CDIM + tid] = s2.w;
  w0[12 * CDIM + tid] = s3.x; w0[13 * CDIM + tid] = s3.y;
  w0[14 * CDIM + tid] = s3.z; w0[15 * CDIM + tid] = s3.w;
}

// acc[256 x TW] += W[256 x kdim](row-major, ld=ldw, cols kcol0..) @ Ys[kdim x TW]
// Packed FFMA2: acc[i][j] holds output rows (tr*16+2i, tr*16+2i+1), col tc*8+j.
__device__ __forceinline__ void gemm_T16x8p(const float* __restrict__ Wg, int ldw,
                                            int kcol0, int kdim,
                                            const float* __restrict__ Ys,
                                            u64 (&acc)[8][8],
                                            float* __restrict__ wp) {
  const int tid = threadIdx.x;
  const int tr = tid >> 4, tc = tid & 15;
  const float* gp = Wg + (size_t)tid * ldw + kcol0;
  float4 st0 = *(const float4*)(gp + 0);
  float4 st1 = *(const float4*)(gp + 4);
  float4 st2 = *(const float4*)(gp + 8);
  float4 st3 = *(const float4*)(gp + 12);
  storePanel256(wp, tid, st0, st1, st2, st3);
  __syncthreads();
  const int P = kdim / PD;
#pragma unroll 1
  for (int p = 0; p < P; p++) {
    if (p + 1 < P) {
      const float* g2 = gp + (p + 1) * PD;
      st0 = *(const float4*)(g2 + 0);
      st1 = *(const float4*)(g2 + 4);
      st2 = *(const float4*)(g2 + 8);
      st3 = *(const float4*)(g2 + 12);
    }
    const float* wb = wp + (p & 1) * (PD * CDIM);
    const float* yb = Ys + p * PD * TW;
#pragma unroll 4
    for (int k = 0; k < PD; k++) {
      const ulonglong2* wr = (const ulonglong2*)(wb + k * CDIM + tr * 16);
      ulonglong2 w01 = wr[0], w23 = wr[1], w45 = wr[2], w67 = wr[3];
      u64 wv[8] = {w01.x, w01.y, w23.x, w23.y, w45.x, w45.y, w67.x, w67.y};
      const float* yr = yb + k * TW + tc * 8;
      float4 b0 = *(const float4*)(yr);
      float4 b1 = *(const float4*)(yr + 4);
      u64 yd[8] = {pack2(b0.x, b0.x), pack2(b0.y, b0.y),
                   pack2(b0.z, b0.z), pack2(b0.w, b0.w),
                   pack2(b1.x, b1.x), pack2(b1.y, b1.y),
                   pack2(b1.z, b1.z), pack2(b1.w, b1.w)};
#pragma unroll
      for (int i = 0; i < 8; i++)
#pragma unroll
        for (int j = 0; j < 8; j++) acc[i][j] = fma2(wv[i], yd[j], acc[i][j]);
    }
    if (p + 1 < P)
      storePanel256(wp + ((p + 1) & 1) * (PD * CDIM), tid, st0, st1, st2, st3);
    __syncthreads();
  }
}

// acc[64 x TW] += W[64 x 256] @ Ys[256 x TW]; packed pairs over rows.
// acc[i][j] holds rows (rg*4+2i, rg*4+2i+1), col tc*8+j.
__device__ __forceinline__ void gemm_T4x8p(const float* __restrict__ Wg,
                                           const float* __restrict__ Ys,
                                           u64 (&acc)[2][8],
                                           float* __restrict__ wp) {
  const int tid = threadIdx.x;
  const int rg = tid >> 4, tc = tid & 15;
  const int lrow = tid >> 2, lk = (tid & 3) * 4;
  const float* gp = Wg + (size_t)lrow * CDIM + lk;
  float4 st = *(const float4*)(gp);
  {
    float* w0 = wp;
    w0[(lk + 0) * 64 + lrow] = st.x;
    w0[(lk + 1) * 64 + lrow] = st.y;
    w0[(lk + 2) * 64 + lrow] = st.z;
    w0[(lk + 3) * 64 + lrow] = st.w;
  }
  __syncthreads();
  const int P = CDIM / PD;
#pragma unroll 1
  for (int p = 0; p < P; p++) {
    if (p + 1 < P) st = *(const float4*)(gp + (p + 1) * PD);
    const float* wb = wp + (p & 1) * (PD * 64);
    const float* yb = Ys + p * PD * TW;
#pragma unroll 4
    for (int k = 0; k < PD; k++) {
      const ulonglong2* wr = (const ulonglong2*)(wb + k * 64 + rg * 4);
      ulonglong2 wq = wr[0];
      u64 wv[2] = {wq.x, wq.y};
      const float* yr = yb + k * TW + tc * 8;
      float4 b0 = *(const float4*)(yr);
      float4 b1 = *(const float4*)(yr + 4);
      u64 yd[8] = {pack2(b0.x, b0.x), pack2(b0.y, b0.y),
                   pack2(b0.z, b0.z), pack2(b0.w, b0.w),
                   pack2(b1.x, b1.x), pack2(b1.y, b1.y),
                   pack2(b1.z, b1.z), pack2(b1.w, b1.w)};
#pragma unroll
      for (int i = 0; i < 2; i++)
#pragma unroll
        for (int j = 0; j < 8; j++) acc[i][j] = fma2(wv[i], yd[j], acc[i][j]);
    }
    if (p + 1 < P) {
      float* wn = wp + ((p + 1) & 1) * (PD * 64);
      wn[(lk + 0) * 64 + lrow] = st.x;
      wn[(lk + 1) * 64 + lrow] = st.y;
      wn[(lk + 2) * 64 + lrow] = st.z;
      wn[(lk + 3) * 64 + lrow] = st.w;
    }
    __syncthreads();
  }
}

__global__ void __launch_bounds__(NTHREADS, 1)
fused_block_kernel(const float* __restrict__ x,
                   const float* __restrict__ ln1_w, const float* __restrict__ ln1_b,
                   const float* __restrict__ qkv_w, const float* __restrict__ qkv_b,
                   const float* __restrict__ out_w, const float* __restrict__ out_b,
                   const float* __restrict__ ln2_w, const float* __restrict__ ln2_b,
                   const float* __restrict__ ffn1_w, const float* __restrict__ ffn1_b,
                   const float* __restrict__ ffn2_w, const float* __restrict__ ffn2_b,
                   float* __restrict__ out) {
  extern __shared__ __align__(16) char smem_raw[];
  Smem* s = reinterpret_cast<Smem*>(smem_raw);
  const int tid = threadIdx.x;
  const int b = blockIdx.x >> 2;
  const int p = blockIdx.x & 3;
  const size_t base = (size_t)b * (CDIM * 4 * NDIM) + (size_t)p * NDIM;

  // ---------- Phase 0: cache small vectors ----------
  for (int i = tid; i < CDIM; i += NTHREADS) {
    float g = ln1_w[i];
    s->g1[i] = g;
    s->be1[i] = ln1_b[i];
    s->g2v[i] = ln2_w[i];
    s->be2[i] = ln2_b[i];
    s->avec[i] = qkv_w[i] * g;   // row 0 of qkv_w = w_q
    s->bvv[i] = qkv_b[1 + CDIM + i];
    s->bov[i] = out_b[i];
    s->bf2v[i] = ffn2_b[i];
  }
  for (int i = tid; i < FDIM; i += NTHREADS) s->bf1v[i] = ffn1_b[i];
  float aP = 0.f, bP = 0.f;
  for (int i = tid; i < CDIM; i += NTHREADS) {
    aP += qkv_w[i] * ln1_w[i];
    bP += qkv_w[i] * ln1_b[i];
  }
  __syncthreads();
  const float A_ = blockSum(aP, s->scratch);
  const float B0_ = blockSum(bP, s->scratch) + qkv_b[0];

  // ---------- Phase 1: LN stats + q per column ----------
#pragma unroll 1
  for (int pass = 0; pass < NDIM / NTHREADS; pass++) {
    const int n = pass * NTHREADS + tid;
    const float* xp = x + base + n;
    float s1 = 0.f, s2 = 0.f, sq = 0.f;
#pragma unroll 8
    for (int c = 0; c < CDIM; c++) {
      float v = __ldg(xp + (size_t)c * CS);
      s1 += v;
      s2 = fmaf(v, v, s2);
      sq = fmaf(s->avec[c], v, sq);
    }
    const float mean = s1 * (1.0f / 256.0f);
    const float var = s2 * (1.0f / 256.0f) - mean * mean;
    const float rstd = rsqrtf(var + EPS);
    s->meanA[n] = mean;
    s->rstdA[n] = rstd;
    s->qA[n] = rstd * (sq - mean * A_) + B0_;
  }
  __syncthreads();

  // ---------- Phase 2: softmax over n, ybar, ctx ----------
  {
    float mx = -3.4e38f;
#pragma unroll
    for (int k = 0; k < 4; k++) mx = fmaxf(mx, s->qA[k * NTHREADS + tid]);
    mx = blockMax(mx, s->scratch);
    float ev[4];
    float ssum = 0.f, usum = 0.f;
#pragma unroll
    for (int k = 0; k < 4; k++) {
      const int i = k * NTHREADS + tid;
      float e = expf(s->qA[i] - mx);
      ev[k] = e;
      ssum += e;
      usum = fmaf(e, s->rstdA[i] * s->meanA[i], usum);
    }
    ssum = blockSum(ssum, s->scratch);
    usum = blockSum(usum, s->scratch);
    const float inv = 1.0f / ssum;
    const float U = usum * inv;
#pragma unroll
    for (int k = 0; k < 4; k++) {
      const int i = k * NTHREADS + tid;
      s->qA[i] = ev[k] * inv * s->rstdA[i];   // u_n = softmax_n * rstd_n
    }
    __syncthreads();

    const int w = tid >> 5, l = tid & 31;
    for (int r = w; r < CDIM; r += 8) {
      const float* xr = x + base + (size_t)r * CS;
      float acc = 0.f;
#pragma unroll 4
      for (int i = l; i < NDIM; i += 32) acc = fmaf(__ldg(xr + i), s->qA[i], acc);
      acc = warpSum(acc);
      if (l == 0) s->ybar[r] = s->g1[r] * (acc - U) + s->be1[r];
    }
    __syncthreads();
    for (int r = w; r < CDIM; r += 8) {
      const float* wr = qkv_w + (size_t)(1 + r) * CDIM;
      float acc = 0.f;
#pragma unroll 4
      for (int i = l; i < CDIM; i += 32) acc = fmaf(__ldg(wr + i), s->ybar[i], acc);
      acc = warpSum(acc);
      if (l == 0) s->ctxv[r] = acc + qkv_b[1 + r];
    }
    __syncthreads();
  }

  // ---------- Phase 3: tiled main pipeline ----------
  const int tr = tid >> 4, tc = tid & 15;
#pragma unroll 1
  for (int it = 0; it < NTILES; it++) {
    const int n0 = it * TW;

    // build y1 tile (yt)
    for (int idx = tid; idx < CDIM * (TW / 4); idx += NTHREADS) {
      const int r = idx >> 5;
      const int j = (idx & 31) << 2;
      float4 xv = *(const float4*)(x + base + (size_t)r * CS + n0 + j);
      float4 mv = *(const float4*)&s->meanA[n0 + j];
      float4 rv = *(const float4*)&s->rstdA[n0 + j];
      const float g = s->g1[r], be = s->be1[r];
      float4 yv;
      yv.x = (xv.x - mv.x) * rv.x * g + be;
      yv.y = (xv.y - mv.y) * rv.y * g + be;
      yv.z = (xv.z - mv.z) * rv.z * g + be;
      yv.w = (xv.w - mv.w) * rv.w * g + be;
      *(float4*)&s->yt[r * TW + j] = yv;
    }
    // (gemm prologue barrier orders yt writes vs reads)

    u64 acc[8][8];
#pragma unroll
    for (int i = 0; i < 8; i++)
#pragma unroll
      for (int j = 0; j < 8; j++) acc[i][j] = 0ull;

    // G1: V = W_v @ Y1 (rows 257..512 of qkv)
    gemm_T16x8p(qkv_w + (size_t)(1 + CDIM) * CDIM, CDIM, 0, CDIM, s->yt, acc, s->wp);
#pragma unroll
    for (int i = 0; i < 8; i++) {
      const int r0 = tr * 16 + 2 * i;
      const float bv0 = s->bvv[r0], cx0 = s->ctxv[r0];
      const float bv1 = s->bvv[r0 + 1], cx1 = s->ctxv[r0 + 1];
      float o0[8], o1[8];
#pragma unroll
      for (int j = 0; j < 8; j++) {
        float2 v = unpack2(acc[i][j]);
        o0[j] = fmaxf(v.x + bv0, 0.f) * cx0;
        o1[j] = fmaxf(v.y + bv1, 0.f) * cx1;
      }
      *(float4*)&s->yt[r0 * TW + tc * 8]           = make_float4(o0[0], o0[1], o0[2], o0[3]);
      *(float4*)&s->yt[r0 * TW + tc * 8 + 4]       = make_float4(o0[4], o0[5], o0[6], o0[7]);
      *(float4*)&s->yt[(r0 + 1) * TW + tc * 8]     = make_float4(o1[0], o1[1], o1[2], o1[3]);
      *(float4*)&s->yt[(r0 + 1) * TW + tc * 8 + 4] = make_float4(o1[4], o1[5], o1[6], o1[7]);
    }

#pragma unroll
    for (int i = 0; i < 8; i++)
#pragma unroll
      for (int j = 0; j < 8; j++) acc[i][j] = 0ull;

    // G2: O = W_out @ attn ; x2 = x + O + b ; LN2 stats
    gemm_T16x8p(out_w, CDIM, 0, CDIM, s->yt, acc, s->wp);
    float s1l[8], s2l[8];
#pragma unroll
    for (int j = 0; j < 8; j++) { s1l[j] = 0.f; s2l[j] = 0.f; }
#pragma unroll
    for (int i = 0; i < 8; i++) {
      const int r0 = tr * 16 + 2 * i;
      const float bo0 = s->bov[r0], bo1 = s->bov[r0 + 1];
      const float* xp0 = x + base + (size_t)r0 * CS + n0 + tc * 8;
      const float* xp1 = xp0 + CS;
      float4 xa0 = *(const float4*)(xp0);
      float4 xb0 = *(const float4*)(xp0 + 4);
      float4 xa1 = *(const float4*)(xp1);
      float4 xb1 = *(const float4*)(xp1 + 4);
      float xs0[8] = {xa0.x, xa0.y, xa0.z, xa0.w, xb0.x, xb0.y, xb0.z, xb0.w};
      float xs1[8] = {xa1.x, xa1.y, xa1.z, xa1.w, xb1.x, xb1.y, xb1.z, xb1.w};
#pragma unroll
      for (int j = 0; j < 8; j++) {
        float2 v = unpack2(acc[i][j]);
        const float v0 = v.x + bo0 + xs0[j];
        const float v1 = v.y + bo1 + xs1[j];
        acc[i][j] = pack2(v0, v1);   // acc now holds x2 (kept through FFN)
        s1l[j] += v0 + v1;
        s2l[j] = fmaf(v0, v0, fmaf(v1, v1, s2l[j]));
      }
    }
    // LN2 reduction (aliased into hbuf)
    {
      float* red1 = s->hbuf;
      float* red2 = s->hbuf + 16 * 132;
#pragma unroll
      for (int j = 0; j < 8; j++) {
        red1[tr * 132 + tc * 8 + j] = s1l[j];
        red2[tr * 132 + tc * 8 + j] = s2l[j];
      }
      __syncthreads();
      if (tid < TW) {
        float m = 0.f, vv = 0.f;
#pragma unroll
        for (int g = 0; g < 16; g++) {
          m += red1[g * 132 + tid];
          vv += red2[g * 132 + tid];
        }
        m *= (1.0f / 256.0f);
        vv = vv * (1.0f / 256.0f) - m * m;
        s->m2s[tid] = m;
        s->r2s[tid] = rsqrtf(vv + EPS);
      }
      __syncthreads();
    }
    // y2 into yt (from packed x2 in acc)
#pragma unroll
    for (int i = 0; i < 8; i++) {
      const int r0 = tr * 16 + 2 * i;
      const float g0 = s->g2v[r0], be0 = s->be2[r0];
      const float g1v = s->g2v[r0 + 1], be1v = s->be2[r0 + 1];
      float y0v[8], y1v[8];
#pragma unroll
      for (int j = 0; j < 8; j++) {
        float2 v = unpack2(acc[i][j]);
        const float m = s->m2s[tc * 8 + j], rr = s->r2s[tc * 8 + j];
        y0v[j] = (v.x - m) * rr * g0 + be0;
        y1v[j] = (v.y - m) * rr * g1v + be1v;
      }
      *(float4*)&s->yt[r0 * TW + tc * 8]           = make_float4(y0v[0], y0v[1], y0v[2], y0v[3]);
      *(float4*)&s->yt[r0 * TW + tc * 8 + 4]       = make_float4(y0v[4], y0v[5], y0v[6], y0v[7]);
      *(float4*)&s->yt[(r0 + 1) * TW + tc * 8]     = make_float4(y1v[0], y1v[1], y1v[2], y1v[3]);
      *(float4*)&s->yt[(r0 + 1) * TW + tc * 8 + 4] = make_float4(y1v[4], y1v[5], y1v[6], y1v[7]);
    }

    // FFN: acc (holding x2) accumulates ffn2 output; H in 64-row blocks
#pragma unroll 1
    for (int hb = 0; hb < FDIM / 64; hb++) {
      u64 a3[2][8];
#pragma unroll
      for (int i = 0; i < 2; i++)
#pragma unroll
        for (int j = 0; j < 8; j++) a3[i][j] = 0ull;
      gemm_T4x8p(ffn1_w + (size_t)hb * 64 * CDIM, s->yt, a3, s->wp);
      const int rg = tid >> 4;
#pragma unroll
      for (int i = 0; i < 2; i++) {
        const int hr0 = rg * 4 + 2 * i;
        const float bf0 = s->bf1v[hb * 64 + hr0];
        const float bf1 = s->bf1v[hb * 64 + hr0 + 1];
        float h0[8], h1[8];
#pragma unroll
        for (int j = 0; j < 8; j++) {
          float2 v = unpack2(a3[i][j]);
          float a = v.x + bf0;
          float c = v.y + bf1;
          h0[j] = (a > 0.f) ? a : 0.1f * a;
          h1[j] = (c > 0.f) ? c : 0.1f * c;
        }
        *(float4*)&s->hbuf[hr0 * TW + tc * 8]           = make_float4(h0[0], h0[1], h0[2], h0[3]);
        *(float4*)&s->hbuf[hr0 * TW + tc * 8 + 4]       = make_float4(h0[4], h0[5], h0[6], h0[7]);
        *(float4*)&s->hbuf[(hr0 + 1) * TW + tc * 8]     = make_float4(h1[0], h1[1], h1[2], h1[3]);
        *(float4*)&s->hbuf[(hr0 + 1) * TW + tc * 8 + 4] = make_float4(h1[4], h1[5], h1[6], h1[7]);
      }
      // G4 partial: acc += W2[:, hb*64..+64) @ Hblk (prologue bar orders hbuf)
      gemm_T16x8p(ffn2_w, FDIM, hb * 64, 64, s->hbuf, acc, s->wp);
    }

    // final: out = x2 + ffn2(H) + b2 (all in acc, packed)
#pragma unroll
    for (int i = 0; i < 8; i++) {
      const int r0 = tr * 16 + 2 * i;
      const float bf0 = s->bf2v[r0], bf1 = s->bf2v[r0 + 1];
      float o0[8], o1[8];
#pragma unroll
      for (int j = 0; j < 8; j++) {
        float2 v = unpack2(acc[i][j]);
        o0[j] = v.x + bf0;
        o1[j] = v.y + bf1;
      }
      float* op0 = out + base + (size_t)r0 * CS + n0 + tc * 8;
      float* op1 = op0 + CS;
      *(float4*)op0       = make_float4(o0[0], o0[1], o0[2], o0[3]);
      *(float4*)(op0 + 4) = make_float4(o0[4], o0[5], o0[6], o0[7]);
      *(float4*)op1       = make_float4(o1[0], o1[1], o1[2], o1[3]);
      *(float4*)(op1 + 4) = make_float4(o1[4], o1[5], o1[6], o1[7]);
    }
  }
}

}  // namespace

extern "C" void kernel_launch(void* const* d_in, const int* in_sizes, int n_in,
                              void* d_out, int out_size) {
  const float* x      = (const float*)d_in[0];
  const float* ln1_w  = (const float*)d_in[1];
  const float* ln1_b  = (const float*)d_in[2];
  const float* qkv_w  = (const float*)d_in[3];
  const float* qkv_b  = (const float*)d_in[4];
  const float* out_w  = (const float*)d_in[5];
  const float* out_b  = (const float*)d_in[6];
  const float* ln2_w  = (const float*)d_in[7];
  const float* ln2_b  = (const float*)d_in[8];
  const float* ffn1_w = (const float*)d_in[9];
  const float* ffn1_b = (const float*)d_in[10];
  const float* ffn2_w = (const float*)d_in[11];
  const float* ffn2_b = (const float*)d_in[12];
  float* out = (float*)d_out;

  const int B = in_sizes[0] / (CDIM * 4 * NDIM);
  const int grid = B * 4;
  const int smem = (int)sizeof(Smem);
  cudaFuncSetAttribute(fused_block_kernel,
                       cudaFuncAttributeMaxDynamicSharedMemorySize, smem);
  fused_block_kernel<<<grid, NTHREADS, smem>>>(
      x, ln1_w, ln1_b, qkv_w, qkv_b, out_w, out_b, ln2_w, ln2_b,
      ffn1_w, ffn1_b, ffn2_w, ffn2_b, out);
}

// round 7
// speedup vs baseline: 1.7281x; 1.0010x over previous
#include <cuda_runtime.h>
#include <cstdint>

namespace {

using u64 = unsigned long long;

constexpr int CDIM = 256;
constexpr int FDIM = 512;
constexpr int NDIM = 1024;
constexpr int TW = 128;            // tile width (positions per tile)
constexpr int NTILES = NDIM / TW;  // 8
constexpr int NTHREADS = 256;
constexpr int PD = 16;             // weight panel depth (k)
constexpr int CS = 4 * NDIM;       // channel stride in x (floats)
constexpr float EPS = 1e-5f;

struct Smem {
  float yt[CDIM * TW];        // y1 / attn / y2 tile (128 KB)
  float hbuf[64 * TW];        // FFN hidden block; aliased as LN2 reduction buf
  float wp[2 * PD * CDIM];    // double-buffered weight panel (32 KB)
  float meanA[NDIM];
  float rstdA[NDIM];
  float qA[NDIM];             // q, then u = softmax*rstd
  float g1[CDIM], be1[CDIM], g2v[CDIM], be2[CDIM], avec[CDIM];
  float ctxv[CDIM], ybar[CDIM], bvv[CDIM], bov[CDIM], bf2v[CDIM];
  float bf1v[FDIM];
  float m2s[TW], r2s[TW];
  float scratch[40];
};

// ---- packed fp32x2 helpers (FFMA2 path, sm_100a) ----
__device__ __forceinline__ u64 fma2(u64 a, u64 b, u64 c) {
  u64 d;
  asm("fma.rn.f32x2 %0, %1, %2, %3;" : "=l"(d) : "l"(a), "l"(b), "l"(c));
  return d;
}
__device__ __forceinline__ u64 pack2(float lo, float hi) {
  u64 d;
  asm("mov.b64 %0, {%1, %2};" : "=l"(d) : "f"(lo), "f"(hi));
  return d;
}
__device__ __forceinline__ float2 unpack2(u64 v) {
  float lo, hi;
  asm("mov.b64 {%0, %1}, %2;" : "=f"(lo), "=f"(hi) : "l"(v));
  return make_float2(lo, hi);
}

__device__ __forceinline__ float warpSum(float v) {
#pragma unroll
  for (int o = 16; o; o >>= 1) v += __shfl_xor_sync(0xffffffffu, v, o);
  return v;
}

__device__ __forceinline__ float blockSum(float v, float* scr) {
  v = warpSum(v);
  const int w = threadIdx.x >> 5;
  if ((threadIdx.x & 31) == 0) scr[w] = v;
  __syncthreads();
  if (threadIdx.x == 0) {
    float t = 0.f;
#pragma unroll
    for (int i = 0; i < NTHREADS / 32; i++) t += scr[i];
    scr[8] = t;
  }
  __syncthreads();
  float r = scr[8];
  __syncthreads();
  return r;
}

__device__ __forceinline__ float blockMax(float v, float* scr) {
#pragma unroll
  for (int o = 16; o; o >>= 1) v = fmaxf(v, __shfl_xor_sync(0xffffffffu, v, o));
  const int w = threadIdx.x >> 5;
  if ((threadIdx.x & 31) == 0) scr[w] = v;
  __syncthreads();
  if (threadIdx.x == 0) {
    float t = scr[0];
#pragma unroll
    for (int i = 1; i < NTHREADS / 32; i++) t = fmaxf(t, scr[i]);
    scr[8] = t;
  }
  __syncthreads();
  float r = scr[8];
  __syncthreads();
  return r;
}

__device__ __forceinline__ void storePanel256(float* w0, int tid,
                                              const float4& s0, const float4& s1,
                                              const float4& s2, const float4& s3) {
  w0[0 * CDIM + tid] = s0.x;  w0[1 * CDIM + tid] = s0.y;
  w0[2 * CDIM + tid] = s0.z;  w0[3 * CDIM + tid] = s0.w;
  w0[4 * CDIM + tid] = s1.x;  w0[5 * CDIM + tid] = s1.y;
  w0[6 * CDIM + tid] = s1.z;  w0[7 * CDIM + tid] = s1.w;
  w0[8 * CDIM + tid] = s2.x;  w0[9 * CDIM + tid] = s2.y;
  w0[10 * CDIM + tid] = s2.z; w0[11 * CDIM + tid] = s2.w;
  w0[12 * CDIM + tid] = s3.x; w0[13 * CDIM + tid] = s3.y;
  w0[14 * CDIM + tid] = s3.z; w0[15 * CDIM + tid] = s3.w;
}

// acc[256 x TW] += W[256 x kdim](row-major, ld=ldw, cols kcol0..) @ Ys[kdim x TW]
// Packed FFMA2: acc[i][j] holds output rows (tr*16+2i, tr*16+2i+1), col tc*8+j.
__device__ __forceinline__ void gemm_T16x8p(const float* __restrict__ Wg, int ldw,
                                            int kcol0, int kdim,
                                            const float* __restrict__ Ys,
                                            u64 (&acc)[8][8],
                                            float* __restrict__ wp) {
  const int tid = threadIdx.x;
  const int tr = tid >> 4, tc = tid & 15;
  const float* gp = Wg + (size_t)tid * ldw + kcol0;
  float4 st0 = *(const float4*)(gp + 0);
  float4 st1 = *(const float4*)(gp + 4);
  float4 st2 = *(const float4*)(gp + 8);
  float4 st3 = *(const float4*)(gp + 12);
  storePanel256(wp, tid, st0, st1, st2, st3);
  __syncthreads();
  const int P = kdim / PD;
#pragma unroll 1
  for (int p = 0; p < P; p++) {
    if (p + 1 < P) {
      const float* g2 = gp + (p + 1) * PD;
      st0 = *(const float4*)(g2 + 0);
      st1 = *(const float4*)(g2 + 4);
      st2 = *(const float4*)(g2 + 8);
      st3 = *(const float4*)(g2 + 12);
    }
    const float* wb = wp + (p & 1) * (PD * CDIM);
    const float* yb = Ys + p * PD * TW;
#pragma unroll 4
    for (int k = 0; k < PD; k++) {
      const ulonglong2* wr = (const ulonglong2*)(wb + k * CDIM + tr * 16);
      ulonglong2 w01 = wr[0], w23 = wr[1], w45 = wr[2], w67 = wr[3];
      u64 wv[8] = {w01.x, w01.y, w23.x, w23.y, w45.x, w45.y, w67.x, w67.y};
      const float* yr = yb + k * TW + tc * 8;
      float4 b0 = *(const float4*)(yr);
      float4 b1 = *(const float4*)(yr + 4);
      u64 yd[8] = {pack2(b0.x, b0.x), pack2(b0.y, b0.y),
                   pack2(b0.z, b0.z), pack2(b0.w, b0.w),
                   pack2(b1.x, b1.x), pack2(b1.y, b1.y),
                   pack2(b1.z, b1.z), pack2(b1.w, b1.w)};
#pragma unroll
      for (int i = 0; i < 8; i++)
#pragma unroll
        for (int j = 0; j < 8; j++) acc[i][j] = fma2(wv[i], yd[j], acc[i][j]);
    }
    if (p + 1 < P)
      storePanel256(wp + ((p + 1) & 1) * (PD * CDIM), tid, st0, st1, st2, st3);
    __syncthreads();
  }
}

// acc[64 x TW] += W[64 x 256] @ Ys[256 x TW]; packed pairs over rows.
// acc[i][j] holds rows (rg*4+2i, rg*4+2i+1), col tc*8+j.
__device__ __forceinline__ void gemm_T4x8p(const float* __restrict__ Wg,
                                           const float* __restrict__ Ys,
                                           u64 (&acc)[2][8],
                                           float* __restrict__ wp) {
  const int tid = threadIdx.x;
  const int rg = tid >> 4, tc = tid & 15;
  const int lrow = tid >> 2, lk = (tid & 3) * 4;
  const float* gp = Wg + (size_t)lrow * CDIM + lk;
  float4 st = *(const float4*)(gp);
  {
    float* w0 = wp;
    w0[(lk + 0) * 64 + lrow] = st.x;
    w0[(lk + 1) * 64 + lrow] = st.y;
    w0[(lk + 2) * 64 + lrow] = st.z;
    w0[(lk + 3) * 64 + lrow] = st.w;
  }
  __syncthreads();
  const int P = CDIM / PD;
#pragma unroll 1
  for (int p = 0; p < P; p++) {
    if (p + 1 < P) st = *(const float4*)(gp + (p + 1) * PD);
    const float* wb = wp + (p & 1) * (PD * 64);
    const float* yb = Ys + p * PD * TW;
#pragma unroll 4
    for (int k = 0; k < PD; k++) {
      const ulonglong2* wr = (const ulonglong2*)(wb + k * 64 + rg * 4);
      ulonglong2 wq = wr[0];
      u64 wv[2] = {wq.x, wq.y};
      const float* yr = yb + k * TW + tc * 8;
      float4 b0 = *(const float4*)(yr);
      float4 b1 = *(const float4*)(yr + 4);
      u64 yd[8] = {pack2(b0.x, b0.x), pack2(b0.y, b0.y),
                   pack2(b0.z, b0.z), pack2(b0.w, b0.w),
                   pack2(b1.x, b1.x), pack2(b1.y, b1.y),
                   pack2(b1.z, b1.z), pack2(b1.w, b1.w)};
#pragma unroll
      for (int i = 0; i < 2; i++)
#pragma unroll
        for (int j = 0; j < 8; j++) acc[i][j] = fma2(wv[i], yd[j], acc[i][j]);
    }
    if (p + 1 < P) {
      float* wn = wp + ((p + 1) & 1) * (PD * 64);
      wn[(lk + 0) * 64 + lrow] = st.x;
      wn[(lk + 1) * 64 + lrow] = st.y;
      wn[(lk + 2) * 64 + lrow] = st.z;
      wn[(lk + 3) * 64 + lrow] = st.w;
    }
    __syncthreads();
  }
}

__global__ void __launch_bounds__(NTHREADS, 1)
fused_block_kernel(const float* __restrict__ x,
                   const float* __restrict__ ln1_w, const float* __restrict__ ln1_b,
                   const float* __restrict__ qkv_w, const float* __restrict__ qkv_b,
                   const float* __restrict__ out_w, const float* __restrict__ out_b,
                   const float* __restrict__ ln2_w, const float* __restrict__ ln2_b,
                   const float* __restrict__ ffn1_w, const float* __restrict__ ffn1_b,
                   const float* __restrict__ ffn2_w, const float* __restrict__ ffn2_b,
                   float* __restrict__ out) {
  extern __shared__ __align__(16) char smem_raw[];
  Smem* s = reinterpret_cast<Smem*>(smem_raw);
  const int tid = threadIdx.x;
  const int b = blockIdx.x >> 2;
  const int p = blockIdx.x & 3;
  const size_t base = (size_t)b * (CDIM * 4 * NDIM) + (size_t)p * NDIM;

  // ---------- Phase 0: cache small vectors ----------
  for (int i = tid; i < CDIM; i += NTHREADS) {
    float g = ln1_w[i];
    s->g1[i] = g;
    s->be1[i] = ln1_b[i];
    s->g2v[i] = ln2_w[i];
    s->be2[i] = ln2_b[i];
    s->avec[i] = qkv_w[i] * g;   // row 0 of qkv_w = w_q
    s->bvv[i] = qkv_b[1 + CDIM + i];
    s->bov[i] = out_b[i];
    s->bf2v[i] = ffn2_b[i];
  }
  for (int i = tid; i < FDIM; i += NTHREADS) s->bf1v[i] = ffn1_b[i];
  float aP = 0.f, bP = 0.f;
  for (int i = tid; i < CDIM; i += NTHREADS) {
    aP += qkv_w[i] * ln1_w[i];
    bP += qkv_w[i] * ln1_b[i];
  }
  __syncthreads();
  const float A_ = blockSum(aP, s->scratch);
  const float B0_ = blockSum(bP, s->scratch) + qkv_b[0];

  // ---------- Phase 1: LN stats + q per column ----------
#pragma unroll 1
  for (int pass = 0; pass < NDIM / NTHREADS; pass++) {
    const int n = pass * NTHREADS + tid;
    const float* xp = x + base + n;
    float s1 = 0.f, s2 = 0.f, sq = 0.f;
#pragma unroll 8
    for (int c = 0; c < CDIM; c++) {
      float v = __ldg(xp + (size_t)c * CS);
      s1 += v;
      s2 = fmaf(v, v, s2);
      sq = fmaf(s->avec[c], v, sq);
    }
    const float mean = s1 * (1.0f / 256.0f);
    const float var = s2 * (1.0f / 256.0f) - mean * mean;
    const float rstd = rsqrtf(var + EPS);
    s->meanA[n] = mean;
    s->rstdA[n] = rstd;
    s->qA[n] = rstd * (sq - mean * A_) + B0_;
  }
  __syncthreads();

  // ---------- Phase 2: softmax over n, ybar, ctx ----------
  {
    float mx = -3.4e38f;
#pragma unroll
    for (int k = 0; k < 4; k++) mx = fmaxf(mx, s->qA[k * NTHREADS + tid]);
    mx = blockMax(mx, s->scratch);
    float ev[4];
    float ssum = 0.f, usum = 0.f;
#pragma unroll
    for (int k = 0; k < 4; k++) {
      const int i = k * NTHREADS + tid;
      float e = expf(s->qA[i] - mx);
      ev[k] = e;
      ssum += e;
      usum = fmaf(e, s->rstdA[i] * s->meanA[i], usum);
    }
    ssum = blockSum(ssum, s->scratch);
    usum = blockSum(usum, s->scratch);
    const float inv = 1.0f / ssum;
    const float U = usum * inv;
#pragma unroll
    for (int k = 0; k < 4; k++) {
      const int i = k * NTHREADS + tid;
      s->qA[i] = ev[k] * inv * s->rstdA[i];   // u_n = softmax_n * rstd_n
    }
    __syncthreads();

    const int w = tid >> 5, l = tid & 31;
    for (int r = w; r < CDIM; r += 8) {
      const float* xr = x + base + (size_t)r * CS;
      float acc = 0.f;
#pragma unroll 4
      for (int i = l; i < NDIM; i += 32) acc = fmaf(__ldg(xr + i), s->qA[i], acc);
      acc = warpSum(acc);
      if (l == 0) s->ybar[r] = s->g1[r] * (acc - U) + s->be1[r];
    }
    __syncthreads();
    for (int r = w; r < CDIM; r += 8) {
      const float* wr = qkv_w + (size_t)(1 + r) * CDIM;
      float acc = 0.f;
#pragma unroll 4
      for (int i = l; i < CDIM; i += 32) acc = fmaf(__ldg(wr + i), s->ybar[i], acc);
      acc = warpSum(acc);
      if (l == 0) s->ctxv[r] = acc + qkv_b[1 + r];
    }
    __syncthreads();
  }

  // ---------- Phase 3: tiled main pipeline ----------
  const int tr = tid >> 4, tc = tid & 15;
#pragma unroll 1
  for (int it = 0; it < NTILES; it++) {
    const int n0 = it * TW;

    // build y1 tile (yt)
    for (int idx = tid; idx < CDIM * (TW / 4); idx += NTHREADS) {
      const int r = idx >> 5;
      const int j = (idx & 31) << 2;
      float4 xv = *(const float4*)(x + base + (size_t)r * CS + n0 + j);
      float4 mv = *(const float4*)&s->meanA[n0 + j];
      float4 rv = *(const float4*)&s->rstdA[n0 + j];
      const float g = s->g1[r], be = s->be1[r];
      float4 yv;
      yv.x = (xv.x - mv.x) * rv.x * g + be;
      yv.y = (xv.y - mv.y) * rv.y * g + be;
      yv.z = (xv.z - mv.z) * rv.z * g + be;
      yv.w = (xv.w - mv.w) * rv.w * g + be;
      *(float4*)&s->yt[r * TW + j] = yv;
    }
    // (gemm prologue barrier orders yt writes vs reads)

    u64 acc[8][8];
#pragma unroll
    for (int i = 0; i < 8; i++)
#pragma unroll
      for (int j = 0; j < 8; j++) acc[i][j] = 0ull;

    // G1: V = W_v @ Y1 (rows 257..512 of qkv)
    gemm_T16x8p(qkv_w + (size_t)(1 + CDIM) * CDIM, CDIM, 0, CDIM, s->yt, acc, s->wp);
#pragma unroll
    for (int i = 0; i < 8; i++) {
      const int r0 = tr * 16 + 2 * i;
      const float bv0 = s->bvv[r0], cx0 = s->ctxv[r0];
      const float bv1 = s->bvv[r0 + 1], cx1 = s->ctxv[r0 + 1];
      float o0[8], o1[8];
#pragma unroll
      for (int j = 0; j < 8; j++) {
        float2 v = unpack2(acc[i][j]);
        o0[j] = fmaxf(v.x + bv0, 0.f) * cx0;
        o1[j] = fmaxf(v.y + bv1, 0.f) * cx1;
      }
      *(float4*)&s->yt[r0 * TW + tc * 8]           = make_float4(o0[0], o0[1], o0[2], o0[3]);
      *(float4*)&s->yt[r0 * TW + tc * 8 + 4]       = make_float4(o0[4], o0[5], o0[6], o0[7]);
      *(float4*)&s->yt[(r0 + 1) * TW + tc * 8]     = make_float4(o1[0], o1[1], o1[2], o1[3]);
      *(float4*)&s->yt[(r0 + 1) * TW + tc * 8 + 4] = make_float4(o1[4], o1[5], o1[6], o1[7]);
    }

#pragma unroll
    for (int i = 0; i < 8; i++)
#pragma unroll
      for (int j = 0; j < 8; j++) acc[i][j] = 0ull;

    // G2: O = W_out @ attn ; x2 = x + O + b ; LN2 stats
    gemm_T16x8p(out_w, CDIM, 0, CDIM, s->yt, acc, s->wp);
    float s1l[8], s2l[8];
#pragma unroll
    for (int j = 0; j < 8; j++) { s1l[j] = 0.f; s2l[j] = 0.f; }
#pragma unroll
    for (int i = 0; i < 8; i++) {
      const int r0 = tr * 16 + 2 * i;
      const float bo0 = s->bov[r0], bo1 = s->bov[r0 + 1];
      const float* xp0 = x + base + (size_t)r0 * CS + n0 + tc * 8;
      const float* xp1 = xp0 + CS;
      float4 xa0 = *(const float4*)(xp0);
      float4 xb0 = *(const float4*)(xp0 + 4);
      float4 xa1 = *(const float4*)(xp1);
      float4 xb1 = *(const float4*)(xp1 + 4);
      float xs0[8] = {xa0.x, xa0.y, xa0.z, xa0.w, xb0.x, xb0.y, xb0.z, xb0.w};
      float xs1[8] = {xa1.x, xa1.y, xa1.z, xa1.w, xb1.x, xb1.y, xb1.z, xb1.w};
#pragma unroll
      for (int j = 0; j < 8; j++) {
        float2 v = unpack2(acc[i][j]);
        const float v0 = v.x + bo0 + xs0[j];
        const float v1 = v.y + bo1 + xs1[j];
        acc[i][j] = pack2(v0, v1);   // acc now holds x2 (kept through FFN)
        s1l[j] += v0 + v1;
        s2l[j] = fmaf(v0, v0, fmaf(v1, v1, s2l[j]));
      }
    }
    // LN2 reduction (aliased into hbuf)
    {
      float* red1 = s->hbuf;
      float* red2 = s->hbuf + 16 * 132;
#pragma unroll
      for (int j = 0; j < 8; j++) {
        red1[tr * 132 + tc * 8 + j] = s1l[j];
        red2[tr * 132 + tc * 8 + j] = s2l[j];
      }
      __syncthreads();
      if (tid < TW) {
        float m = 0.f, vv = 0.f;
#pragma unroll
        for (int g = 0; g < 16; g++) {
          m += red1[g * 132 + tid];
          vv += red2[g * 132 + tid];
        }
        m *= (1.0f / 256.0f);
        vv = vv * (1.0f / 256.0f) - m * m;
        s->m2s[tid] = m;
        s->r2s[tid] = rsqrtf(vv + EPS);
      }
      __syncthreads();
    }
    // y2 into yt (from packed x2 in acc)
#pragma unroll
    for (int i = 0; i < 8; i++) {
      const int r0 = tr * 16 + 2 * i;
      const float g0 = s->g2v[r0], be0 = s->be2[r0];
      const float g1v = s->g2v[r0 + 1], be1v = s->be2[r0 + 1];
      float y0v[8], y1v[8];
#pragma unroll
      for (int j = 0; j < 8; j++) {
        float2 v = unpack2(acc[i][j]);
        const float m = s->m2s[tc * 8 + j], rr = s->r2s[tc * 8 + j];
        y0v[j] = (v.x - m) * rr * g0 + be0;
        y1v[j] = (v.y - m) * rr * g1v + be1v;
      }
      *(float4*)&s->yt[r0 * TW + tc * 8]           = make_float4(y0v[0], y0v[1], y0v[2], y0v[3]);
      *(float4*)&s->yt[r0 * TW + tc * 8 + 4]       = make_float4(y0v[4], y0v[5], y0v[6], y0v[7]);
      *(float4*)&s->yt[(r0 + 1) * TW + tc * 8]     = make_float4(y1v[0], y1v[1], y1v[2], y1v[3]);
      *(float4*)&s->yt[(r0 + 1) * TW + tc * 8 + 4] = make_float4(y1v[4], y1v[5], y1v[6], y1v[7]);
    }

    // FFN: acc (holding x2) accumulates ffn2 output; H in 64-row blocks
#pragma unroll 1
    for (int hb = 0; hb < FDIM / 64; hb++) {
      u64 a3[2][8];
#pragma unroll
      for (int i = 0; i < 2; i++)
#pragma unroll
        for (int j = 0; j < 8; j++) a3[i][j] = 0ull;
      gemm_T4x8p(ffn1_w + (size_t)hb * 64 * CDIM, s->yt, a3, s->wp);
      const int rg = tid >> 4;
#pragma unroll
      for (int i = 0; i < 2; i++) {
        const int hr0 = rg * 4 + 2 * i;
        const float bf0 = s->bf1v[hb * 64 + hr0];
        const float bf1 = s->bf1v[hb * 64 + hr0 + 1];
        float h0[8], h1[8];
#pragma unroll
        for (int j = 0; j < 8; j++) {
          float2 v = unpack2(a3[i][j]);
          float a = v.x + bf0;
          float c = v.y + bf1;
          h0[j] = (a > 0.f) ? a : 0.1f * a;
          h1[j] = (c > 0.f) ? c : 0.1f * c;
        }
        *(float4*)&s->hbuf[hr0 * TW + tc * 8]           = make_float4(h0[0], h0[1], h0[2], h0[3]);
        *(float4*)&s->hbuf[hr0 * TW + tc * 8 + 4]       = make_float4(h0[4], h0[5], h0[6], h0[7]);
        *(float4*)&s->hbuf[(hr0 + 1) * TW + tc * 8]     = make_float4(h1[0], h1[1], h1[2], h1[3]);
        *(float4*)&s->hbuf[(hr0 + 1) * TW + tc * 8 + 4] = make_float4(h1[4], h1[5], h1[6], h1[7]);
      }
      // G4 partial: acc += W2[:, hb*64..+64) @ Hblk (prologue bar orders hbuf)
      gemm_T16x8p(ffn2_w, FDIM, hb * 64, 64, s->hbuf, acc, s->wp);
    }

    // final: out = x2 + ffn2(H) + b2 (all in acc, packed)
#pragma unroll
    for (int i = 0; i < 8; i++) {
      const int r0 = tr * 16 + 2 * i;
      const float bf0 = s->bf2v[r0], bf1 = s->bf2v[r0 + 1];
      float o0[8], o1[8];
#pragma unroll
      for (int j = 0; j < 8; j++) {
        float2 v = unpack2(acc[i][j]);
        o0[j] = v.x + bf0;
        o1[j] = v.y + bf1;
      }
      float* op0 = out + base + (size_t)r0 * CS + n0 + tc * 8;
      float* op1 = op0 + CS;
      *(float4*)op0       = make_float4(o0[0], o0[1], o0[2], o0[3]);
      *(float4*)(op0 + 4) = make_float4(o0[4], o0[5], o0[6], o0[7]);
      *(float4*)op1       = make_float4(o1[0], o1[1], o1[2], o1[3]);
      *(float4*)(op1 + 4) = make_float4(o1[4], o1[5], o1[6], o1[7]);
    }
  }
}

}  // namespace

extern "C" void kernel_launch(void* const* d_in, const int* in_sizes, int n_in,
                              void* d_out, int out_size) {
  const float* x      = (const float*)d_in[0];
  const float* ln1_w  = (const float*)d_in[1];
  const float* ln1_b  = (const float*)d_in[2];
  const float* qkv_w  = (const float*)d_in[3];
  const float* qkv_b  = (const float*)d_in[4];
  const float* out_w  = (const float*)d_in[5];
  const float* out_b  = (const float*)d_in[6];
  const float* ln2_w  = (const float*)d_in[7];
  const float* ln2_b  = (const float*)d_in[8];
  const float* ffn1_w = (const float*)d_in[9];
  const float* ffn1_b = (const float*)d_in[10];
  const float* ffn2_w = (const float*)d_in[11];
  const float* ffn2_b = (const float*)d_in[12];
  float* out = (float*)d_out;

  const int B = in_sizes[0] / (CDIM * 4 * NDIM);
  const int grid = B * 4;
  const int smem = (int)sizeof(Smem);
  cudaFuncSetAttribute(fused_block_kernel,
                       cudaFuncAttributeMaxDynamicSharedMemorySize, smem);
  fused_block_kernel<<<grid, NTHREADS, smem>>>(
      x, ln1_w, ln1_b, qkv_w, qkv_b, out_w, out_b, ln2_w, ln2_b,
      ffn1_w, ffn1_b, ffn2_w, ffn2_b, out);
}